// round 10
// baseline (speedup 1.0000x reference)
#include <cuda_runtime.h>
#include <cstdint>

static constexpr int S_LEN   = 8192;
static constexpr int Dh      = 64;
static constexpr int OUTROWS = 7936;   // S - WINDOW/2
static constexpr int TK      = 32;     // keys per tile
static constexpr int PAD     = 68;     // smem row stride (f32 words); 68 % 8 == 4 -> LDSM conflict-free
static constexpr int NT      = 128;    // 4 warps x 32 q-rows = 128 queries per CTA, 2 CTAs/SM

__device__ __forceinline__ uint32_t f2tf32(float x) {
    uint32_t r; asm("cvt.rna.tf32.f32 %0, %1;" : "=r"(r) : "f"(x)); return r;
}
__device__ __forceinline__ float ex2f(float x) {
    float r; asm("ex2.approx.ftz.f32 %0, %1;" : "=f"(r) : "f"(x)); return r;
}
__device__ __forceinline__ void mma8(float d[4], const uint32_t a[4], const uint32_t* b) {
    asm("mma.sync.aligned.m16n8k8.row.col.f32.tf32.tf32.f32 "
        "{%0,%1,%2,%3}, {%4,%5,%6,%7}, {%8,%9}, {%0,%1,%2,%3};"
        : "+f"(d[0]), "+f"(d[1]), "+f"(d[2]), "+f"(d[3])
        : "r"(a[0]), "r"(a[1]), "r"(a[2]), "r"(a[3]), "r"(b[0]), "r"(b[1]));
}
__device__ __forceinline__ void ldsm4(uint32_t r[4], uint32_t saddr) {
    asm volatile("ldmatrix.sync.aligned.m8n8.x4.shared.b16 {%0,%1,%2,%3}, [%4];"
                 : "=r"(r[0]), "=r"(r[1]), "=r"(r[2]), "=r"(r[3]) : "r"(saddr));
}
__device__ __forceinline__ float4 cvt4(float4 a) {
    return { __uint_as_float(f2tf32(a.x)), __uint_as_float(f2tf32(a.y)),
             __uint_as_float(f2tf32(a.z)), __uint_as_float(f2tf32(a.w)) };
}

__global__ __launch_bounds__(NT, 2)
void swa_mma(const float* __restrict__ qg, const float* __restrict__ kg,
             const float* __restrict__ vg, float* __restrict__ outg)
{
    __shared__ float kbuf[2][TK * PAD];   // 8.5 KB each
    __shared__ float vbuf[2][TK * PAD];   // rotation-swizzled: d' = (d + 4*(key&7)) & 63

    const int bh = blockIdx.y, qb = blockIdx.x;
    int kstart, klen;
    if (qb < 2) { kstart = 0; klen = 256; }
    else        { kstart = 256 + 512 * ((qb - 2) >> 2); klen = 512; }
    const int nt = 1 + klen / TK;   // tile 0 = 32 global keys, then local tiles

    const int tid  = threadIdx.x;
    const int warp = tid >> 5, lane = tid & 31;
    const int g = lane >> 2, tig = lane & 3;

    const float C = 0.125f * 1.44269504088896340736f;  // scale * log2(e), folded into Q
    const size_t kvbase = (size_t)bh * S_LEN * Dh;

    // LDSM lane addressing for K fragments (4 matrices per x4).
    const int krow = ((lane >> 4) << 3) | (lane & 7);   // row within 16-row pair-block
    const int kcol = ((lane >> 3) & 1) * 4;             // d half (0 or 4)

    // V fragment address constants (rotation swizzle).
    const int t68  = tig * 68;
    const int rot0 = g + 4 * tig;        // b0 inner index pre-&63
    const int rot1 = rot0 + 16;         // b1 (key+4 -> rotation +16)

    // ---- Q fragments (scaled by C, then RNA-rounded tf32): [kb=8][rb=2][4] ----
    uint32_t qf[8][2][4];
    {
        const float* qp = qg + kvbase + (size_t)(qb * 128 + warp * 32) * Dh;
        #pragma unroll
        for (int kb = 0; kb < 8; kb++)
            #pragma unroll
            for (int rb = 0; rb < 2; rb++) {
                const int r0 = rb * 16 + g;
                const int c0 = kb * 8 + tig;
                qf[kb][rb][0] = f2tf32(qp[(r0    ) * Dh + c0    ] * C);
                qf[kb][rb][1] = f2tf32(qp[(r0 + 8) * Dh + c0    ] * C);
                qf[kb][rb][2] = f2tf32(qp[(r0    ) * Dh + c0 + 4] * C);
                qf[kb][rb][3] = f2tf32(qp[(r0 + 8) * Dh + c0 + 4] * C);
            }
    }

    float o[2][8][4];
    #pragma unroll
    for (int rb = 0; rb < 2; rb++)
        #pragma unroll
        for (int nb = 0; nb < 8; nb++)
            #pragma unroll
            for (int i = 0; i < 4; i++) o[rb][nb][i] = 0.f;
    // Per-thread partial softmax denominators (reduced across the quad at the end).
    float lrow[2][2] = {{0.f, 0.f}, {0.f, 0.f}};

    const float4* kp4 = (const float4*)(kg + kvbase);
    const float4* vp4 = (const float4*)(vg + kvbase);
    float4 stk[4], stv[4];

    const uint32_t ksm0 = (uint32_t)__cvta_generic_to_shared(kbuf[0]);
    const uint32_t ksm1 = (uint32_t)__cvta_generic_to_shared(kbuf[1]);
    const uint32_t vsm0 = (uint32_t)__cvta_generic_to_shared(vbuf[0]);
    const uint32_t vsm1 = (uint32_t)__cvta_generic_to_shared(vbuf[1]);

    // Prologue: stage tile 0 (32 global keys). 512 float4 per matrix, 4 per thread.
    {
        #pragma unroll
        for (int j = 0; j < 4; j++) { stk[j] = kp4[tid + NT * j]; stv[j] = vp4[tid + NT * j]; }
        #pragma unroll
        for (int j = 0; j < 4; j++) {
            const int f4i = tid + NT * j, row = f4i >> 4, c = f4i & 15;
            *(float4*)&kbuf[0][row * PAD + c * 4] = cvt4(stk[j]);
            const int w = row * PAD + ((4 * c + 4 * (row & 7)) & 63);
            *(float4*)&vbuf[0][w] = cvt4(stv[j]);
        }
    }
    __syncthreads();

    for (int t = 0; t < nt; t++) {
        const bool pf = (t + 1) < nt;
        const int cur = t & 1, nxt = cur ^ 1;
        const uint32_t ks = cur ? ksm1 : ksm0;
        const uint32_t vs = cur ? vsm1 : vsm0;

        if (pf) {
            const size_t roff = (size_t)(kstart + t * TK) * (Dh / 4);
            #pragma unroll
            for (int j = 0; j < 4; j++) stk[j] = kp4[roff + tid + NT * j];
        }

        // ---- S = (C*Q) K^T (K frags via ldmatrix.x4, conflict-free) ----
        float sf[2][4][4];
        #pragma unroll
        for (int rb = 0; rb < 2; rb++)
            #pragma unroll
            for (int nb = 0; nb < 4; nb++)
                #pragma unroll
                for (int i = 0; i < 4; i++) sf[rb][nb][i] = 0.f;
        #pragma unroll
        for (int kb = 0; kb < 8; kb++) {
            #pragma unroll
            for (int p = 0; p < 2; p++) {
                uint32_t kf[4];
                const uint32_t a = ks + (uint32_t)(((p * 16 + krow) * PAD + kb * 8 + kcol) * 4);
                ldsm4(kf, a);
                mma8(sf[0][2 * p],     qf[kb][0], kf);
                mma8(sf[1][2 * p],     qf[kb][1], kf);
                mma8(sf[0][2 * p + 1], qf[kb][0], kf + 2);
                mma8(sf[1][2 * p + 1], qf[kb][1], kf + 2);
            }
        }

        // ---- static softmax: p = 2^s, accumulate per-thread partial l ----
        // (no online max: scores are O(10) in log2 domain, f32 cannot overflow)
        #pragma unroll
        for (int rb = 0; rb < 2; rb++) {
            float s0 = 0.f, s1 = 0.f;
            #pragma unroll
            for (int nb = 0; nb < 4; nb++) {
                float p0 = ex2f(sf[rb][nb][0]);
                float p1 = ex2f(sf[rb][nb][1]);
                float p2 = ex2f(sf[rb][nb][2]);
                float p3 = ex2f(sf[rb][nb][3]);
                s0 += p0 + p1; s1 += p2 + p3;
                sf[rb][nb][0] = __uint_as_float(f2tf32(p0));
                sf[rb][nb][1] = __uint_as_float(f2tf32(p1));
                sf[rb][nb][2] = __uint_as_float(f2tf32(p2));
                sf[rb][nb][3] = __uint_as_float(f2tf32(p3));
            }
            lrow[rb][0] += s0;
            lrow[rb][1] += s1;
        }

        // Drain K prefetch into next buffer; prefetch next V.
        if (pf) {
            #pragma unroll
            for (int j = 0; j < 4; j++) {
                const int f4i = tid + NT * j, row = f4i >> 4, c = f4i & 15;
                *(float4*)&kbuf[nxt][row * PAD + c * 4] = cvt4(stk[j]);
            }
            const size_t roff = (size_t)(kstart + t * TK) * (Dh / 4);
            #pragma unroll
            for (int j = 0; j < 4; j++) stv[j] = vp4[roff + tid + NT * j];
        }

        // ---- O += P V ---- (P frags from S frags via quad shuffle)
        const int src0 = (lane & ~3) | (tig >> 1);
        const int src2 = src0 + 2;
        const bool odd = (lane & 1);
        #pragma unroll
        for (int kb = 0; kb < 4; kb++) {
            uint32_t a[2][4];
            #pragma unroll
            for (int rb = 0; rb < 2; rb++) {
                const float e0 = sf[rb][kb][0], e1 = sf[rb][kb][1];
                const float e2 = sf[rb][kb][2], e3 = sf[rb][kb][3];
                float t00 = __shfl_sync(0xffffffffu, e0, src0);
                float t01 = __shfl_sync(0xffffffffu, e1, src0);
                float t20 = __shfl_sync(0xffffffffu, e2, src0);
                float t21 = __shfl_sync(0xffffffffu, e3, src0);
                float t40 = __shfl_sync(0xffffffffu, e0, src2);
                float t41 = __shfl_sync(0xffffffffu, e1, src2);
                float t60 = __shfl_sync(0xffffffffu, e2, src2);
                float t61 = __shfl_sync(0xffffffffu, e3, src2);
                a[rb][0] = __float_as_uint(odd ? t01 : t00);
                a[rb][1] = __float_as_uint(odd ? t21 : t20);
                a[rb][2] = __float_as_uint(odd ? t41 : t40);
                a[rb][3] = __float_as_uint(odd ? t61 : t60);
            }
            const uint32_t vb0 = vs + (uint32_t)((kb * 544 + t68) * 4);
            const uint32_t vb1 = vb0 + 272 * 4;   // key+4 row
            #pragma unroll
            for (int nb = 0; nb < 8; nb++) {
                uint32_t b[2];
                asm volatile("ld.shared.b32 %0, [%1];" : "=r"(b[0])
                             : "r"(vb0 + (uint32_t)(((nb * 8 + rot0) & 63) * 4)));
                asm volatile("ld.shared.b32 %0, [%1];" : "=r"(b[1])
                             : "r"(vb1 + (uint32_t)(((nb * 8 + rot1) & 63) * 4)));
                mma8(o[0][nb], a[0], b);
                mma8(o[1][nb], a[1], b);
            }
        }

        // Drain V prefetch (rotation swizzle), flip buffers.
        if (pf) {
            #pragma unroll
            for (int j = 0; j < 4; j++) {
                const int f4i = tid + NT * j, row = f4i >> 4, c = f4i & 15;
                const int w = row * PAD + ((4 * c + 4 * (row & 7)) & 63);
                *(float4*)&vbuf[nxt][w] = cvt4(stv[j]);
            }
            __syncthreads();
        }
    }

    // ---- final l reduction (once, not per tile) + normalize + store ----
    #pragma unroll
    for (int rb = 0; rb < 2; rb++) {
        float l0 = lrow[rb][0], l1 = lrow[rb][1];
        l0 += __shfl_xor_sync(0xffffffffu, l0, 1);
        l0 += __shfl_xor_sync(0xffffffffu, l0, 2);
        l1 += __shfl_xor_sync(0xffffffffu, l1, 1);
        l1 += __shfl_xor_sync(0xffffffffu, l1, 2);
        const float inv0 = 1.f / l0;
        const float inv1 = 1.f / l1;
        const int row0 = qb * 128 + warp * 32 + rb * 16 + g;
        float* op0 = outg + ((size_t)bh * OUTROWS + row0) * Dh;
        float* op1 = op0 + 8 * Dh;
        #pragma unroll
        for (int nb = 0; nb < 8; nb++) {
            const int col = nb * 8 + 2 * tig;
            float2 v0 = { o[rb][nb][0] * inv0, o[rb][nb][1] * inv0 };
            *(float2*)(op0 + col) = v0;
            float2 v1 = { o[rb][nb][2] * inv1, o[rb][nb][3] * inv1 };
            *(float2*)(op1 + col) = v1;
        }
    }
}

extern "C" void kernel_launch(void* const* d_in, const int* in_sizes, int n_in,
                              void* d_out, int out_size)
{
    const float* q = (const float*)d_in[0];
    const float* k = (const float*)d_in[1];
    const float* v = (const float*)d_in[2];
    float* out = (float*)d_out;

    dim3 grid(62, 32);   // 62 q-blocks of 128 rows x 32 (b,h)
    swa_mma<<<grid, NT>>>(q, k, v, out);
}

// round 11
// speedup vs baseline: 1.5820x; 1.5820x over previous
#include <cuda_runtime.h>
#include <cstdint>

static constexpr int S_LEN   = 8192;
static constexpr int Dh      = 64;
static constexpr int OUTROWS = 7936;   // S - WINDOW/2
static constexpr int TK      = 32;     // keys per tile
static constexpr int PAD     = 68;     // smem row stride (f32 words); 68 % 8 == 4 -> LDSM conflict-free
static constexpr int NT      = 128;    // 4 warps x 32 q-rows = 128 queries per CTA, 2 CTAs/SM

__device__ __forceinline__ uint32_t f2tf32(float x) {
    uint32_t r; asm("cvt.rna.tf32.f32 %0, %1;" : "=r"(r) : "f"(x)); return r;
}
__device__ __forceinline__ float ex2f(float x) {
    float r; asm("ex2.approx.ftz.f32 %0, %1;" : "=f"(r) : "f"(x)); return r;
}
__device__ __forceinline__ void mma8(float d[4], const uint32_t a[4], const uint32_t* b) {
    asm("mma.sync.aligned.m16n8k8.row.col.f32.tf32.tf32.f32 "
        "{%0,%1,%2,%3}, {%4,%5,%6,%7}, {%8,%9}, {%0,%1,%2,%3};"
        : "+f"(d[0]), "+f"(d[1]), "+f"(d[2]), "+f"(d[3])
        : "r"(a[0]), "r"(a[1]), "r"(a[2]), "r"(a[3]), "r"(b[0]), "r"(b[1]));
}
__device__ __forceinline__ void ldsm4(uint32_t r[4], uint32_t saddr) {
    asm volatile("ldmatrix.sync.aligned.m8n8.x4.shared.b16 {%0,%1,%2,%3}, [%4];"
                 : "=r"(r[0]), "=r"(r[1]), "=r"(r[2]), "=r"(r[3]) : "r"(saddr));
}
__device__ __forceinline__ float4 cvt4(float4 a) {
    return { __uint_as_float(f2tf32(a.x)), __uint_as_float(f2tf32(a.y)),
             __uint_as_float(f2tf32(a.z)), __uint_as_float(f2tf32(a.w)) };
}

__global__ __launch_bounds__(NT, 2)
void swa_mma(const float* __restrict__ qg, const float* __restrict__ kg,
             const float* __restrict__ vg, float* __restrict__ outg)
{
    __shared__ float kbuf[2][TK * PAD];   // 8.5 KB each
    __shared__ float vbuf[2][TK * PAD];   // swizzled: d' = (d + 32*((key>>1)&1)) & 63

    const int bh = blockIdx.y, qb = blockIdx.x;
    int kstart, klen;
    if (qb < 2) { kstart = 0; klen = 256; }
    else        { kstart = 256 + 512 * ((qb - 2) >> 2); klen = 512; }
    const int nt = 1 + klen / TK;   // tile 0 = 32 global keys, then local tiles

    const int tid  = threadIdx.x;
    const int warp = tid >> 5, lane = tid & 31;
    const int g = lane >> 2, tig = lane & 3;

    const float C = 0.125f * 1.44269504088896340736f;  // scale * log2(e)
    const size_t kvbase = (size_t)bh * S_LEN * Dh;

    // LDSM lane addressing for K fragments (4 matrices per x4).
    const int krow = ((lane >> 4) << 3) | (lane & 7);   // row within 16-row pair-block
    const int kcol = ((lane >> 3) & 1) * 4;             // d half (0 or 4)

    // V fragment address constants (permuted-A scheme):
    // B-frag slot tig -> V row 8kb+2*tig (b0) / 8kb+2*tig+1 (b1); col g.
    // Swizzle offset depends only on tig parity for these rows.
    const int cg = g + ((tig & 1) << 5);   // col pre-&63 (adds the swizzle rotation)

    // ---- Q fragments (RNA-rounded tf32): [kb=8][rb=2][4] ----
    uint32_t qf[8][2][4];
    {
        const float* qp = qg + kvbase + (size_t)(qb * 128 + warp * 32) * Dh;
        #pragma unroll
        for (int kb = 0; kb < 8; kb++)
            #pragma unroll
            for (int rb = 0; rb < 2; rb++) {
                const int r0 = rb * 16 + g;
                const int c0 = kb * 8 + tig;
                qf[kb][rb][0] = f2tf32(qp[(r0    ) * Dh + c0    ]);
                qf[kb][rb][1] = f2tf32(qp[(r0 + 8) * Dh + c0    ]);
                qf[kb][rb][2] = f2tf32(qp[(r0    ) * Dh + c0 + 4]);
                qf[kb][rb][3] = f2tf32(qp[(r0 + 8) * Dh + c0 + 4]);
            }
    }

    float o[2][8][4];
    #pragma unroll
    for (int rb = 0; rb < 2; rb++)
        #pragma unroll
        for (int nb = 0; nb < 8; nb++)
            #pragma unroll
            for (int i = 0; i < 4; i++) o[rb][nb][i] = 0.f;
    float mrow[2][2] = {{-1e30f, -1e30f}, {-1e30f, -1e30f}};
    float lrow[2][2] = {{0.f, 0.f}, {0.f, 0.f}};

    const float4* kp4 = (const float4*)(kg + kvbase);
    const float4* vp4 = (const float4*)(vg + kvbase);
    float4 stk[4], stv[4];

    const uint32_t ksm0 = (uint32_t)__cvta_generic_to_shared(kbuf[0]);
    const uint32_t ksm1 = (uint32_t)__cvta_generic_to_shared(kbuf[1]);
    const uint32_t vsm0 = (uint32_t)__cvta_generic_to_shared(vbuf[0]);
    const uint32_t vsm1 = (uint32_t)__cvta_generic_to_shared(vbuf[1]);

    // Prologue: stage tile 0 (32 global keys). 512 float4 per matrix, 4 per thread.
    {
        #pragma unroll
        for (int j = 0; j < 4; j++) { stk[j] = kp4[tid + NT * j]; stv[j] = vp4[tid + NT * j]; }
        #pragma unroll
        for (int j = 0; j < 4; j++) {
            const int f4i = tid + NT * j, row = f4i >> 4, c = f4i & 15;
            *(float4*)&kbuf[0][row * PAD + c * 4] = cvt4(stk[j]);
            const int w = row * PAD + ((4 * c + (((row >> 1) & 1) << 5)) & 63);
            *(float4*)&vbuf[0][w] = cvt4(stv[j]);
        }
    }
    __syncthreads();

    for (int t = 0; t < nt; t++) {
        const bool pf = (t + 1) < nt;
        const int cur = t & 1, nxt = cur ^ 1;
        const uint32_t ks = cur ? ksm1 : ksm0;
        const uint32_t vs = cur ? vsm1 : vsm0;

        if (pf) {
            const size_t roff = (size_t)(kstart + t * TK) * (Dh / 4);
            #pragma unroll
            for (int j = 0; j < 4; j++) stk[j] = kp4[roff + tid + NT * j];
        }

        // ---- S = Q K^T (K frags via ldmatrix.x4, conflict-free) ----
        float sf[2][4][4];
        #pragma unroll
        for (int rb = 0; rb < 2; rb++)
            #pragma unroll
            for (int nb = 0; nb < 4; nb++)
                #pragma unroll
                for (int i = 0; i < 4; i++) sf[rb][nb][i] = 0.f;
        #pragma unroll
        for (int kb = 0; kb < 8; kb++) {
            #pragma unroll
            for (int p = 0; p < 2; p++) {
                uint32_t kf[4];
                const uint32_t a = ks + (uint32_t)(((p * 16 + krow) * PAD + kb * 8 + kcol) * 4);
                ldsm4(kf, a);
                mma8(sf[0][2 * p],     qf[kb][0], kf);
                mma8(sf[1][2 * p],     qf[kb][1], kf);
                mma8(sf[0][2 * p + 1], qf[kb][0], kf + 2);
                mma8(sf[1][2 * p + 1], qf[kb][1], kf + 2);
            }
        }

        // ---- online softmax ----
        #pragma unroll
        for (int rb = 0; rb < 2; rb++) {
            float r0 = -1e30f, r1 = -1e30f;
            #pragma unroll
            for (int nb = 0; nb < 4; nb++) {
                r0 = fmaxf(r0, fmaxf(sf[rb][nb][0], sf[rb][nb][1]));
                r1 = fmaxf(r1, fmaxf(sf[rb][nb][2], sf[rb][nb][3]));
            }
            r0 = fmaxf(r0, __shfl_xor_sync(0xffffffffu, r0, 1));
            r0 = fmaxf(r0, __shfl_xor_sync(0xffffffffu, r0, 2));
            r1 = fmaxf(r1, __shfl_xor_sync(0xffffffffu, r1, 1));
            r1 = fmaxf(r1, __shfl_xor_sync(0xffffffffu, r1, 2));
            const float mn0 = fmaxf(mrow[rb][0], r0);
            const float mn1 = fmaxf(mrow[rb][1], r1);
            const float al0 = ex2f((mrow[rb][0] - mn0) * C);
            const float al1 = ex2f((mrow[rb][1] - mn1) * C);
            mrow[rb][0] = mn0; mrow[rb][1] = mn1;
            const float mb0 = mn0 * C, mb1 = mn1 * C;
            float s0 = 0.f, s1 = 0.f;
            #pragma unroll
            for (int nb = 0; nb < 4; nb++) {
                float p0 = ex2f(fmaf(sf[rb][nb][0], C, -mb0));
                float p1 = ex2f(fmaf(sf[rb][nb][1], C, -mb0));
                float p2 = ex2f(fmaf(sf[rb][nb][2], C, -mb1));
                float p3 = ex2f(fmaf(sf[rb][nb][3], C, -mb1));
                s0 += p0 + p1; s1 += p2 + p3;
                sf[rb][nb][0] = __uint_as_float(f2tf32(p0));
                sf[rb][nb][1] = __uint_as_float(f2tf32(p1));
                sf[rb][nb][2] = __uint_as_float(f2tf32(p2));
                sf[rb][nb][3] = __uint_as_float(f2tf32(p3));
            }
            s0 += __shfl_xor_sync(0xffffffffu, s0, 1);
            s0 += __shfl_xor_sync(0xffffffffu, s0, 2);
            s1 += __shfl_xor_sync(0xffffffffu, s1, 1);
            s1 += __shfl_xor_sync(0xffffffffu, s1, 2);
            lrow[rb][0] = lrow[rb][0] * al0 + s0;
            lrow[rb][1] = lrow[rb][1] * al1 + s1;
            #pragma unroll
            for (int nb = 0; nb < 8; nb++) {
                o[rb][nb][0] *= al0; o[rb][nb][1] *= al0;
                o[rb][nb][2] *= al1; o[rb][nb][3] *= al1;
            }
        }

        // Drain K prefetch into next buffer; prefetch next V.
        if (pf) {
            #pragma unroll
            for (int j = 0; j < 4; j++) {
                const int f4i = tid + NT * j, row = f4i >> 4, c = f4i & 15;
                *(float4*)&kbuf[nxt][row * PAD + c * 4] = cvt4(stk[j]);
            }
            const size_t roff = (size_t)(kstart + t * TK) * (Dh / 4);
            #pragma unroll
            for (int j = 0; j < 4; j++) stv[j] = vp4[roff + tid + NT * j];
        }

        // ---- O += P V ----
        // Permuted-A: A-frag column c holds key 2c (c<4) / 2(c-4)+1 (c>=4), so the
        // S C-fragment registers ARE the A-fragment ({c0,c2,c1,c3}) with zero data
        // movement; B-frag compensates by fetching V rows 8kb+2*tig and 8kb+2*tig+1.
        #pragma unroll
        for (int kb = 0; kb < 4; kb++) {
            const uint32_t a0[4] = { __float_as_uint(sf[0][kb][0]), __float_as_uint(sf[0][kb][2]),
                                     __float_as_uint(sf[0][kb][1]), __float_as_uint(sf[0][kb][3]) };
            const uint32_t a1[4] = { __float_as_uint(sf[1][kb][0]), __float_as_uint(sf[1][kb][2]),
                                     __float_as_uint(sf[1][kb][1]), __float_as_uint(sf[1][kb][3]) };
            const uint32_t rowbase = vs + (uint32_t)(((kb * 8 + 2 * tig) * PAD) * 4);
            #pragma unroll
            for (int nb = 0; nb < 8; nb++) {
                const uint32_t coff = (uint32_t)(((nb * 8 + cg) & 63) * 4);
                uint32_t b[2];
                asm volatile("ld.shared.b32 %0, [%1];" : "=r"(b[0]) : "r"(rowbase + coff));
                asm volatile("ld.shared.b32 %0, [%1];" : "=r"(b[1]) : "r"(rowbase + PAD * 4 + coff));
                mma8(o[0][nb], a0, b);
                mma8(o[1][nb], a1, b);
            }
        }

        // Drain V prefetch (parity swizzle), flip buffers.
        if (pf) {
            #pragma unroll
            for (int j = 0; j < 4; j++) {
                const int f4i = tid + NT * j, row = f4i >> 4, c = f4i & 15;
                const int w = row * PAD + ((4 * c + (((row >> 1) & 1) << 5)) & 63);
                *(float4*)&vbuf[nxt][w] = cvt4(stv[j]);
            }
            __syncthreads();
        }
    }

    // ---- normalize + store ----
    #pragma unroll
    for (int rb = 0; rb < 2; rb++) {
        const float inv0 = 1.f / lrow[rb][0];
        const float inv1 = 1.f / lrow[rb][1];
        const int row0 = qb * 128 + warp * 32 + rb * 16 + g;
        float* op0 = outg + ((size_t)bh * OUTROWS + row0) * Dh;
        float* op1 = op0 + 8 * Dh;
        #pragma unroll
        for (int nb = 0; nb < 8; nb++) {
            const int col = nb * 8 + 2 * tig;
            float2 v0 = { o[rb][nb][0] * inv0, o[rb][nb][1] * inv0 };
            *(float2*)(op0 + col) = v0;
            float2 v1 = { o[rb][nb][2] * inv1, o[rb][nb][3] * inv1 };
            *(float2*)(op1 + col) = v1;
        }
    }
}

extern "C" void kernel_launch(void* const* d_in, const int* in_sizes, int n_in,
                              void* d_out, int out_size)
{
    const float* q = (const float*)d_in[0];
    const float* k = (const float*)d_in[1];
    const float* v = (const float*)d_in[2];
    float* out = (float*)d_out;

    dim3 grid(62, 32);   // 62 q-blocks of 128 rows x 32 (b,h)
    swa_mma<<<grid, NT>>>(q, k, v, out);
}

// round 12
// speedup vs baseline: 1.8112x; 1.1449x over previous
#include <cuda_runtime.h>
#include <cstdint>

static constexpr int S_LEN   = 8192;
static constexpr int Dh      = 64;
static constexpr int OUTROWS = 7936;   // S - WINDOW/2
static constexpr int TK      = 32;     // keys per tile
static constexpr int PAD     = 68;     // smem row stride (f32 words); 68 % 8 == 4 -> LDSM conflict-free
static constexpr int NT      = 128;    // 4 warps x 32 q-rows = 128 queries per CTA, 2 CTAs/SM

__device__ __forceinline__ uint32_t f2tf32(float x) {
    uint32_t r; asm("cvt.rna.tf32.f32 %0, %1;" : "=r"(r) : "f"(x)); return r;
}
__device__ __forceinline__ float ex2f(float x) {
    float r; asm("ex2.approx.ftz.f32 %0, %1;" : "=f"(r) : "f"(x)); return r;
}
__device__ __forceinline__ void mma8(float d[4], const uint32_t a[4], const uint32_t* b) {
    asm("mma.sync.aligned.m16n8k8.row.col.f32.tf32.tf32.f32 "
        "{%0,%1,%2,%3}, {%4,%5,%6,%7}, {%8,%9}, {%0,%1,%2,%3};"
        : "+f"(d[0]), "+f"(d[1]), "+f"(d[2]), "+f"(d[3])
        : "r"(a[0]), "r"(a[1]), "r"(a[2]), "r"(a[3]), "r"(b[0]), "r"(b[1]));
}
__device__ __forceinline__ void ldsm4(uint32_t r[4], uint32_t saddr) {
    asm volatile("ldmatrix.sync.aligned.m8n8.x4.shared.b16 {%0,%1,%2,%3}, [%4];"
                 : "=r"(r[0]), "=r"(r[1]), "=r"(r[2]), "=r"(r[3]) : "r"(saddr));
}
__device__ __forceinline__ void cpa16(uint32_t dst, const void* src) {
    asm volatile("cp.async.cg.shared.global [%0], [%1], 16;" :: "r"(dst), "l"(src));
}

__global__ __launch_bounds__(NT, 2)
void swa_mma(const float* __restrict__ qg, const float* __restrict__ kg,
             const float* __restrict__ vg, float* __restrict__ outg)
{
    __shared__ float kbuf[2][TK * PAD];   // 8.5 KB each
    __shared__ float vbuf[2][TK * PAD];   // swizzled: d' = (d + 32*((key>>1)&1)) & 63

    const int bh = blockIdx.y, qb = blockIdx.x;
    int kstart, klen;
    if (qb < 2) { kstart = 0; klen = 256; }
    else        { kstart = 256 + 512 * ((qb - 2) >> 2); klen = 512; }
    const int nt = 1 + klen / TK;   // tile 0 = 32 global keys, then local tiles

    const int tid  = threadIdx.x;
    const int warp = tid >> 5, lane = tid & 31;
    const int g = lane >> 2, tig = lane & 3;

    const float C = 0.125f * 1.44269504088896340736f;  // scale * log2(e)
    const size_t kvbase = (size_t)bh * S_LEN * Dh;

    // LDSM lane addressing for K fragments (4 matrices per x4).
    const int krow = ((lane >> 4) << 3) | (lane & 7);   // row within 16-row pair-block
    const int kcol = ((lane >> 3) & 1) * 4;             // d half (0 or 4)

    // V fragment address constants (permuted-A scheme).
    const int cg = g + ((tig & 1) << 5);   // col pre-&63 (adds the swizzle rotation)

    // Per-thread cp.async staging addresses (4 x 16B per matrix per tile).
    // f4i = tid + NT*j ; row = f4i>>4 ; c = f4i&15
    int krowj[4], kdst[4], vdst[4];
    #pragma unroll
    for (int j = 0; j < 4; j++) {
        const int f4i = tid + NT * j, row = f4i >> 4, c = f4i & 15;
        krowj[j] = f4i;                                   // float4 index within tile
        kdst[j] = (row * PAD + c * 4) * 4;                // byte offset
        vdst[j] = (row * PAD + ((4 * c + (((row >> 1) & 1) << 5)) & 63)) * 4;
    }

    // ---- Q fragments (RNA-rounded tf32): [kb=8][rb=2][4] ----
    uint32_t qf[8][2][4];
    {
        const float* qp = qg + kvbase + (size_t)(qb * 128 + warp * 32) * Dh;
        #pragma unroll
        for (int kb = 0; kb < 8; kb++)
            #pragma unroll
            for (int rb = 0; rb < 2; rb++) {
                const int r0 = rb * 16 + g;
                const int c0 = kb * 8 + tig;
                qf[kb][rb][0] = f2tf32(qp[(r0    ) * Dh + c0    ]);
                qf[kb][rb][1] = f2tf32(qp[(r0 + 8) * Dh + c0    ]);
                qf[kb][rb][2] = f2tf32(qp[(r0    ) * Dh + c0 + 4]);
                qf[kb][rb][3] = f2tf32(qp[(r0 + 8) * Dh + c0 + 4]);
            }
    }

    float o[2][8][4];
    #pragma unroll
    for (int rb = 0; rb < 2; rb++)
        #pragma unroll
        for (int nb = 0; nb < 8; nb++)
            #pragma unroll
            for (int i = 0; i < 4; i++) o[rb][nb][i] = 0.f;
    float mrow[2][2] = {{-1e30f, -1e30f}, {-1e30f, -1e30f}};
    float lrow[2][2] = {{0.f, 0.f}, {0.f, 0.f}};

    const float4* kp4 = (const float4*)(kg + kvbase);
    const float4* vp4 = (const float4*)(vg + kvbase);

    const uint32_t ksm0 = (uint32_t)__cvta_generic_to_shared(kbuf[0]);
    const uint32_t ksm1 = (uint32_t)__cvta_generic_to_shared(kbuf[1]);
    const uint32_t vsm0 = (uint32_t)__cvta_generic_to_shared(vbuf[0]);
    const uint32_t vsm1 = (uint32_t)__cvta_generic_to_shared(vbuf[1]);

    // Prologue: async-stage tile 0 (32 global keys).
    {
        #pragma unroll
        for (int j = 0; j < 4; j++) {
            cpa16(ksm0 + kdst[j], kp4 + krowj[j]);
            cpa16(vsm0 + vdst[j], vp4 + krowj[j]);
        }
        asm volatile("cp.async.commit_group;");
        asm volatile("cp.async.wait_group 0;" ::: "memory");
    }
    __syncthreads();

    for (int t = 0; t < nt; t++) {
        const bool pf = (t + 1) < nt;
        const int cur = t & 1;
        const uint32_t ks = cur ? ksm1 : ksm0;
        const uint32_t vs = cur ? vsm1 : vsm0;
        const uint32_t ksn = cur ? ksm0 : ksm1;
        const uint32_t vsn = cur ? vsm0 : vsm1;

        // Async-prefetch next tile straight into the other smem buffer.
        if (pf) {
            const size_t roff = (size_t)(kstart + t * TK) * (Dh / 4);
            #pragma unroll
            for (int j = 0; j < 4; j++) {
                cpa16(ksn + kdst[j], kp4 + roff + krowj[j]);
                cpa16(vsn + vdst[j], vp4 + roff + krowj[j]);
            }
            asm volatile("cp.async.commit_group;");
        }

        // ---- S = Q K^T (K frags via ldmatrix.x4, conflict-free) ----
        float sf[2][4][4];
        #pragma unroll
        for (int rb = 0; rb < 2; rb++)
            #pragma unroll
            for (int nb = 0; nb < 4; nb++)
                #pragma unroll
                for (int i = 0; i < 4; i++) sf[rb][nb][i] = 0.f;
        #pragma unroll
        for (int kb = 0; kb < 8; kb++) {
            #pragma unroll
            for (int p = 0; p < 2; p++) {
                uint32_t kf[4];
                const uint32_t a = ks + (uint32_t)(((p * 16 + krow) * PAD + kb * 8 + kcol) * 4);
                ldsm4(kf, a);
                mma8(sf[0][2 * p],     qf[kb][0], kf);
                mma8(sf[1][2 * p],     qf[kb][1], kf);
                mma8(sf[0][2 * p + 1], qf[kb][0], kf + 2);
                mma8(sf[1][2 * p + 1], qf[kb][1], kf + 2);
            }
        }

        // ---- online softmax ----
        #pragma unroll
        for (int rb = 0; rb < 2; rb++) {
            float r0 = -1e30f, r1 = -1e30f;
            #pragma unroll
            for (int nb = 0; nb < 4; nb++) {
                r0 = fmaxf(r0, fmaxf(sf[rb][nb][0], sf[rb][nb][1]));
                r1 = fmaxf(r1, fmaxf(sf[rb][nb][2], sf[rb][nb][3]));
            }
            r0 = fmaxf(r0, __shfl_xor_sync(0xffffffffu, r0, 1));
            r0 = fmaxf(r0, __shfl_xor_sync(0xffffffffu, r0, 2));
            r1 = fmaxf(r1, __shfl_xor_sync(0xffffffffu, r1, 1));
            r1 = fmaxf(r1, __shfl_xor_sync(0xffffffffu, r1, 2));
            const float mn0 = fmaxf(mrow[rb][0], r0);
            const float mn1 = fmaxf(mrow[rb][1], r1);
            const float al0 = ex2f((mrow[rb][0] - mn0) * C);
            const float al1 = ex2f((mrow[rb][1] - mn1) * C);
            mrow[rb][0] = mn0; mrow[rb][1] = mn1;
            const float mb0 = mn0 * C, mb1 = mn1 * C;
            float s0 = 0.f, s1 = 0.f;
            #pragma unroll
            for (int nb = 0; nb < 4; nb++) {
                float p0 = ex2f(fmaf(sf[rb][nb][0], C, -mb0));
                float p1 = ex2f(fmaf(sf[rb][nb][1], C, -mb0));
                float p2 = ex2f(fmaf(sf[rb][nb][2], C, -mb1));
                float p3 = ex2f(fmaf(sf[rb][nb][3], C, -mb1));
                s0 += p0 + p1; s1 += p2 + p3;
                sf[rb][nb][0] = __uint_as_float(f2tf32(p0));
                sf[rb][nb][1] = __uint_as_float(f2tf32(p1));
                sf[rb][nb][2] = __uint_as_float(f2tf32(p2));
                sf[rb][nb][3] = __uint_as_float(f2tf32(p3));
            }
            s0 += __shfl_xor_sync(0xffffffffu, s0, 1);
            s0 += __shfl_xor_sync(0xffffffffu, s0, 2);
            s1 += __shfl_xor_sync(0xffffffffu, s1, 1);
            s1 += __shfl_xor_sync(0xffffffffu, s1, 2);
            lrow[rb][0] = lrow[rb][0] * al0 + s0;
            lrow[rb][1] = lrow[rb][1] * al1 + s1;
            #pragma unroll
            for (int nb = 0; nb < 8; nb++) {
                o[rb][nb][0] *= al0; o[rb][nb][1] *= al0;
                o[rb][nb][2] *= al1; o[rb][nb][3] *= al1;
            }
        }

        // ---- O += P V ----
        // Permuted-A: A-frag column c holds key 2c (c<4) / 2(c-4)+1 (c>=4); the S
        // C-fragment registers ARE the A-fragment ({c0,c2,c1,c3}) with zero data
        // movement; B-frag compensates by fetching V rows 8kb+2*tig and 8kb+2*tig+1.
        #pragma unroll
        for (int kb = 0; kb < 4; kb++) {
            const uint32_t a0[4] = { __float_as_uint(sf[0][kb][0]), __float_as_uint(sf[0][kb][2]),
                                     __float_as_uint(sf[0][kb][1]), __float_as_uint(sf[0][kb][3]) };
            const uint32_t a1[4] = { __float_as_uint(sf[1][kb][0]), __float_as_uint(sf[1][kb][2]),
                                     __float_as_uint(sf[1][kb][1]), __float_as_uint(sf[1][kb][3]) };
            const uint32_t rowbase = vs + (uint32_t)(((kb * 8 + 2 * tig) * PAD) * 4);
            #pragma unroll
            for (int nb = 0; nb < 8; nb++) {
                const uint32_t coff = (uint32_t)(((nb * 8 + cg) & 63) * 4);
                uint32_t b[2];
                asm volatile("ld.shared.b32 %0, [%1];" : "=r"(b[0]) : "r"(rowbase + coff));
                asm volatile("ld.shared.b32 %0, [%1];" : "=r"(b[1]) : "r"(rowbase + PAD * 4 + coff));
                mma8(o[0][nb], a0, b);
                mma8(o[1][nb], a1, b);
            }
        }

        // Tile boundary: wait for the async prefetch, then flip.
        if (pf) {
            asm volatile("cp.async.wait_group 0;" ::: "memory");
            __syncthreads();
        }
    }

    // ---- normalize + store ----
    #pragma unroll
    for (int rb = 0; rb < 2; rb++) {
        const float inv0 = 1.f / lrow[rb][0];
        const float inv1 = 1.f / lrow[rb][1];
        const int row0 = qb * 128 + warp * 32 + rb * 16 + g;
        float* op0 = outg + ((size_t)bh * OUTROWS + row0) * Dh;
        float* op1 = op0 + 8 * Dh;
        #pragma unroll
        for (int nb = 0; nb < 8; nb++) {
            const int col = nb * 8 + 2 * tig;
            float2 v0 = { o[rb][nb][0] * inv0, o[rb][nb][1] * inv0 };
            *(float2*)(op0 + col) = v0;
            float2 v1 = { o[rb][nb][2] * inv1, o[rb][nb][3] * inv1 };
            *(float2*)(op1 + col) = v1;
        }
    }
}

extern "C" void kernel_launch(void* const* d_in, const int* in_sizes, int n_in,
                              void* d_out, int out_size)
{
    const float* q = (const float*)d_in[0];
    const float* k = (const float*)d_in[1];
    const float* v = (const float*)d_in[2];
    float* out = (float*)d_out;

    dim3 grid(62, 32);   // 62 q-blocks of 128 rows x 32 (b,h)
    swa_mma<<<grid, NT>>>(q, k, v, out);
}